// round 1
// baseline (speedup 1.0000x reference)
#include <cuda_runtime.h>
#include <math.h>

// Problem constants (max sizes for static scratch; runtime dims come from in_sizes)
#define NMAX 100000
#define EMAX 1600000
#define GMAX 1024
#define D    128

// ---------------- static device scratch (no runtime allocation) ----------------
__device__ int   g_deg[NMAX];      // in-degree + 1 (self loop)
__device__ float g_dinv[NMAX];     // deg^-1/2
__device__ int   g_off[NMAX];      // CSR offsets (exclusive scan of deg-1)
__device__ int   g_cur[NMAX];      // fill cursors
__device__ int   g_csr[EMAX];      // source node per (dst-sorted) edge
__device__ int   g_part[256];      // scan partials
__device__ int   g_gcnt[GMAX];     // nodes per graph
__device__ int   g_goff[GMAX];     // graph start offsets (batch is sorted)
__device__ float g_P[(size_t)NMAX * D];  // GEMM output / agg input
__device__ float g_H[(size_t)NMAX * D];  // agg output / next GEMM input

// ---------------- init ----------------
__global__ void k_init(int n, int g) {
    int i = blockIdx.x * blockDim.x + threadIdx.x;
    int stride = gridDim.x * blockDim.x;
    for (int j = i; j < n; j += stride) { g_deg[j] = 1; g_cur[j] = 0; }
    for (int j = i; j < g; j += stride) { g_gcnt[j] = 0; }
}

// ---------------- degree count (dst side) ----------------
__global__ void k_count(const int* __restrict__ ei, int E) {
    int e = blockIdx.x * blockDim.x + threadIdx.x;
    if (e < E) atomicAdd(&g_deg[ei[E + e]], 1);
}

// ---------------- exclusive scan of (deg-1), 3-kernel ----------------
__global__ void k_scanA(int n) {
    __shared__ int sm[1024];
    int tid = threadIdx.x;
    int i = blockIdx.x * 1024 + tid;
    int v = 0;
    if (i < n) {
        int dg = g_deg[i];
        v = dg - 1;
        g_dinv[i] = rsqrtf((float)dg);
    }
    sm[tid] = v;
    __syncthreads();
    for (int ofs = 1; ofs < 1024; ofs <<= 1) {
        int t = (tid >= ofs) ? sm[tid - ofs] : 0;
        __syncthreads();
        sm[tid] += t;
        __syncthreads();
    }
    if (i < n) g_off[i] = sm[tid] - v;           // exclusive
    if (tid == 1023) g_part[blockIdx.x] = sm[tid];
}

__global__ void k_scanB(int nb) {
    __shared__ int sm[256];
    int tid = threadIdx.x;
    int v = (tid < nb) ? g_part[tid] : 0;
    sm[tid] = v;
    __syncthreads();
    for (int ofs = 1; ofs < 256; ofs <<= 1) {
        int t = (tid >= ofs) ? sm[tid - ofs] : 0;
        __syncthreads();
        sm[tid] += t;
        __syncthreads();
    }
    if (tid < nb) g_part[tid] = sm[tid] - v;     // exclusive
}

__global__ void k_scanC(int n) {
    int i = blockIdx.x * 1024 + threadIdx.x;
    if (i < n) g_off[i] += g_part[blockIdx.x];
}

// ---------------- CSR fill ----------------
__global__ void k_fill(const int* __restrict__ ei, int E) {
    int e = blockIdx.x * blockDim.x + threadIdx.x;
    if (e < E) {
        int r = ei[e];
        int c = ei[E + e];
        int pos = atomicAdd(&g_cur[c], 1);
        g_csr[g_off[c] + pos] = r;
    }
}

// ---------------- tf32 GEMM: C[M,128] = A[M,128] @ W[128,128] ----------------
__device__ __forceinline__ unsigned f2tf(float f) {
    unsigned u;
    asm("cvt.rna.tf32.f32 %0, %1;" : "=r"(u) : "f"(f));
    return u;
}

#define GEMM_SMEM (2 * 128 * 132 * 4)

__global__ __launch_bounds__(256, 1) void k_gemm(const float* __restrict__ A,
                                                 const float* __restrict__ W,
                                                 float* __restrict__ C, int M) {
    extern __shared__ unsigned smem[];
    unsigned* Ws = smem;              // [128][132] tf32
    unsigned* As = smem + 128 * 132;  // [128][132] tf32
    int tid = threadIdx.x;
    int m0 = blockIdx.x * 128;

    const float4* W4 = (const float4*)W;
    const float4* A4 = (const float4*)A;
#pragma unroll
    for (int j = 0; j < 16; j++) {
        int idx = tid + j * 256;
        int row = idx >> 5;
        int c4 = idx & 31;
        float4 v = W4[row * 32 + c4];
        unsigned* p = &Ws[row * 132 + c4 * 4];
        p[0] = f2tf(v.x); p[1] = f2tf(v.y); p[2] = f2tf(v.z); p[3] = f2tf(v.w);
    }
#pragma unroll
    for (int j = 0; j < 16; j++) {
        int idx = tid + j * 256;
        int row = idx >> 5;
        int c4 = idx & 31;
        int gr = m0 + row;
        float4 v = (gr < M) ? A4[(size_t)gr * 32 + c4] : make_float4(0.f, 0.f, 0.f, 0.f);
        unsigned* p = &As[row * 132 + c4 * 4];
        p[0] = f2tf(v.x); p[1] = f2tf(v.y); p[2] = f2tf(v.z); p[3] = f2tf(v.w);
    }
    __syncthreads();

    int lane = tid & 31;
    int wid = tid >> 5;
    int g = lane >> 2;     // groupID
    int tg = lane & 3;     // thread-in-group
    int wr = wid * 16;     // warp row base within tile

    float acc[64];
#pragma unroll
    for (int i = 0; i < 64; i++) acc[i] = 0.f;

#pragma unroll
    for (int k0 = 0; k0 < 16; k0++) {
        int kk = k0 * 8;
        unsigned a0 = As[(wr + g) * 132 + kk + tg];
        unsigned a1 = As[(wr + g + 8) * 132 + kk + tg];
        unsigned a2 = As[(wr + g) * 132 + kk + tg + 4];
        unsigned a3 = As[(wr + g + 8) * 132 + kk + tg + 4];
        const unsigned* b0p = &Ws[(kk + tg) * 132 + g];
        const unsigned* b1p = &Ws[(kk + tg + 4) * 132 + g];
#pragma unroll
        for (int n0 = 0; n0 < 16; n0++) {
            unsigned b0 = b0p[n0 * 8];
            unsigned b1 = b1p[n0 * 8];
            float* c = &acc[n0 * 4];
            asm volatile(
                "mma.sync.aligned.m16n8k8.row.col.f32.tf32.tf32.f32 "
                "{%0,%1,%2,%3}, {%4,%5,%6,%7}, {%8,%9}, {%0,%1,%2,%3};"
                : "+f"(c[0]), "+f"(c[1]), "+f"(c[2]), "+f"(c[3])
                : "r"(a0), "r"(a1), "r"(a2), "r"(a3), "r"(b0), "r"(b1));
        }
    }

    int r0 = m0 + wr + g;
    int r1 = r0 + 8;
#pragma unroll
    for (int n0 = 0; n0 < 16; n0++) {
        int col = n0 * 8 + 2 * tg;
        if (r0 < M) {
            float2 v; v.x = acc[n0 * 4 + 0]; v.y = acc[n0 * 4 + 1];
            *(float2*)(C + (size_t)r0 * 128 + col) = v;
        }
        if (r1 < M) {
            float2 v; v.x = acc[n0 * 4 + 2]; v.y = acc[n0 * 4 + 3];
            *(float2*)(C + (size_t)r1 * 128 + col) = v;
        }
    }
}

// ---------------- aggregation: warp per dst, gather via CSR ----------------
__global__ void k_agg(const float* __restrict__ hin, float* __restrict__ hout,
                      const float* __restrict__ bias, int n) {
    int t = blockIdx.x * blockDim.x + threadIdx.x;
    int d = t >> 5;
    if (d >= n) return;
    int lane = t & 31;

    const float4* h4 = (const float4*)hin;
    float di = g_dinv[d];
    float4 a = h4[(size_t)d * 32 + lane];
    float ws = di * di;                       // self-loop weight
    float4 acc;
    acc.x = ws * a.x; acc.y = ws * a.y; acc.z = ws * a.z; acc.w = ws * a.w;

    int s0 = g_off[d];
    int e = g_deg[d] - 1;
    int s_nxt = (e > 0) ? g_csr[s0] : 0;
    for (int i = 0; i < e; i++) {
        int s = s_nxt;
        if (i + 1 < e) s_nxt = g_csr[s0 + i + 1];
        float w = di * g_dinv[s];
        float4 v = h4[(size_t)s * 32 + lane];
        acc.x += w * v.x; acc.y += w * v.y; acc.z += w * v.z; acc.w += w * v.w;
    }
    float4 b = ((const float4*)bias)[lane];
    acc.x = fmaxf(acc.x + b.x, 0.f);
    acc.y = fmaxf(acc.y + b.y, 0.f);
    acc.z = fmaxf(acc.z + b.z, 0.f);
    acc.w = fmaxf(acc.w + b.w, 0.f);
    ((float4*)hout)[(size_t)d * 32 + lane] = acc;
}

// ---------------- graph counts + scan ----------------
__global__ void k_gcount(const int* __restrict__ batch, int n) {
    int i = blockIdx.x * blockDim.x + threadIdx.x;
    if (i < n) atomicAdd(&g_gcnt[batch[i]], 1);
}

__global__ void k_gscan(int Gn) {
    __shared__ int sm[1024];
    int t = threadIdx.x;
    int v = (t < Gn) ? g_gcnt[t] : 0;
    sm[t] = v;
    __syncthreads();
    for (int ofs = 1; ofs < 1024; ofs <<= 1) {
        int tt = (t >= ofs) ? sm[t - ofs] : 0;
        __syncthreads();
        sm[t] += tt;
        __syncthreads();
    }
    if (t < Gn) g_goff[t] = sm[t] - v;   // exclusive -> start index
}

// ---------------- mean pool + head MLP (fused), one block per graph ----------------
__global__ void k_pool(const float* __restrict__ u,
                       const float* __restrict__ Wh1, const float* __restrict__ bh1,
                       const float* __restrict__ Wh2, const float* __restrict__ bh2,
                       float* __restrict__ out) {
    __shared__ float hcat[192];
    __shared__ float mid[128];
    int g = blockIdx.x;
    int t = threadIdx.x;   // 128 threads

    int start = g_goff[g];
    int cnt = g_gcnt[g];
    float acc = 0.f;
    for (int i = 0; i < cnt; i++) acc += g_H[(size_t)(start + i) * 128 + t];
    hcat[t] = acc / fmaxf((float)cnt, 1.f);
    if (t < 64) hcat[128 + t] = u[g * 64 + t];
    __syncthreads();

    float m = bh1[t];
#pragma unroll 4
    for (int k = 0; k < 192; k++) m += hcat[k] * Wh1[k * 128 + t];
    mid[t] = fmaxf(m, 0.f);
    __syncthreads();

    if (t < 2) {
        float o = bh2[t];
        for (int k = 0; k < 128; k++) o += mid[k] * Wh2[k * 2 + t];
        out[g * 2 + t] = o;
    }
}

// ---------------- launch ----------------
extern "C" void kernel_launch(void* const* d_in, const int* in_sizes, int n_in,
                              void* d_out, int out_size) {
    const float* x     = (const float*)d_in[0];
    const int*   ei    = (const int*)d_in[1];
    const float* u     = (const float*)d_in[2];
    const int*   batch = (const int*)d_in[3];
    int wi = (n_in >= 13) ? 5 : 4;   // skip scalar batch_size input if present
    const float* W1  = (const float*)d_in[wi + 0];
    const float* b1  = (const float*)d_in[wi + 1];
    const float* W2  = (const float*)d_in[wi + 2];
    const float* b2  = (const float*)d_in[wi + 3];
    const float* Wh1 = (const float*)d_in[wi + 4];
    const float* bh1 = (const float*)d_in[wi + 5];
    const float* Wh2 = (const float*)d_in[wi + 6];
    const float* bh2 = (const float*)d_in[wi + 7];
    float* out = (float*)d_out;

    int N = in_sizes[0] / D;
    int E = in_sizes[1] / 2;
    int G = in_sizes[2] / 64;

    void *pP, *pH;
    cudaGetSymbolAddress(&pP, g_P);
    cudaGetSymbolAddress(&pH, g_H);
    float* P = (float*)pP;
    float* H = (float*)pH;

    cudaFuncSetAttribute(k_gemm, cudaFuncAttributeMaxDynamicSharedMemorySize, GEMM_SMEM);

    k_init<<<256, 256>>>(N, G);
    k_count<<<(E + 255) / 256, 256>>>(ei, E);
    int nb = (N + 1023) / 1024;
    k_scanA<<<nb, 1024>>>(N);
    k_scanB<<<1, 256>>>(nb);
    k_scanC<<<nb, 1024>>>(N);
    k_fill<<<(E + 255) / 256, 256>>>(ei, E);

    int mb = (N + 127) / 128;
    k_gemm<<<mb, 256, GEMM_SMEM>>>(x, W1, P, N);            // h1pre = x @ W1
    k_agg<<<(N * 32 + 255) / 256, 256>>>(P, H, b1, N);      // h1 = relu(A h1pre + b1)
    k_gemm<<<mb, 256, GEMM_SMEM>>>(H, W2, P, N);            // h2pre = h1 @ W2
    k_agg<<<(N * 32 + 255) / 256, 256>>>(P, H, b2, N);      // h2 = relu(A h2pre + b2)

    k_gcount<<<(N + 255) / 256, 256>>>(batch, N);
    k_gscan<<<1, 1024>>>(G);
    k_pool<<<G, 128>>>(u, Wh1, bh1, Wh2, bh2, out);
}

// round 3
// speedup vs baseline: 1.0994x; 1.0994x over previous
#include <cuda_runtime.h>
#include <cuda_fp16.h>
#include <math.h>

#define NMAX 100000
#define EMAX 1600000
#define GMAX 1024
#define D    128

// ---------------- static device scratch ----------------
__device__ int    g_deg[NMAX];
__device__ float  g_dinv[NMAX];
__device__ int    g_off[NMAX];
__device__ int    g_cur[NMAX];
__device__ int2   g_csrw[EMAX];          // {src, weight-as-int}
__device__ int    g_part[256];
__device__ int    g_gcnt[GMAX];
__device__ int    g_goff[GMAX];
__device__ __half g_Ph[(size_t)NMAX * D];   // GEMM out / agg in (fp16)
__device__ __half g_Hh[(size_t)NMAX * D];   // agg out / next GEMM in / pool in (fp16)

// ---------------- init ----------------
__global__ void k_init(int n, int g) {
    int i = blockIdx.x * blockDim.x + threadIdx.x;
    int stride = gridDim.x * blockDim.x;
    for (int j = i; j < n; j += stride) { g_deg[j] = 1; g_cur[j] = 0; }
    for (int j = i; j < g; j += stride) { g_gcnt[j] = 0; }
}

__global__ void k_count(const int* __restrict__ ei, int E) {
    int e = blockIdx.x * blockDim.x + threadIdx.x;
    if (e < E) atomicAdd(&g_deg[ei[E + e]], 1);
}

__global__ void k_gcount(const int* __restrict__ batch, int n) {
    int i = blockIdx.x * blockDim.x + threadIdx.x;
    if (i < n) atomicAdd(&g_gcnt[batch[i]], 1);
}

// ---------------- scan of (deg-1) ----------------
__global__ void k_scanA(int n) {
    __shared__ int sm[1024];
    int tid = threadIdx.x;
    int i = blockIdx.x * 1024 + tid;
    int v = 0;
    if (i < n) {
        int dg = g_deg[i];
        v = dg - 1;
        g_dinv[i] = rsqrtf((float)dg);
    }
    sm[tid] = v;
    __syncthreads();
    for (int ofs = 1; ofs < 1024; ofs <<= 1) {
        int t = (tid >= ofs) ? sm[tid - ofs] : 0;
        __syncthreads();
        sm[tid] += t;
        __syncthreads();
    }
    if (i < n) g_off[i] = sm[tid] - v;
    if (tid == 1023) g_part[blockIdx.x] = sm[tid];
}

__global__ void k_scanB(int nb) {
    __shared__ int sm[256];
    int tid = threadIdx.x;
    int v = (tid < nb) ? g_part[tid] : 0;
    sm[tid] = v;
    __syncthreads();
    for (int ofs = 1; ofs < 256; ofs <<= 1) {
        int t = (tid >= ofs) ? sm[tid - ofs] : 0;
        __syncthreads();
        sm[tid] += t;
        __syncthreads();
    }
    if (tid < nb) g_part[tid] = sm[tid] - v;
}

__global__ void k_scanC(int n) {
    int i = blockIdx.x * 1024 + threadIdx.x;
    if (i < n) g_off[i] += g_part[blockIdx.x];
}

// ---------------- CSR fill with precomputed edge weight ----------------
__global__ void k_fill(const int* __restrict__ ei, int E) {
    int e = blockIdx.x * blockDim.x + threadIdx.x;
    if (e < E) {
        int r = ei[e];
        int c = ei[E + e];
        int pos = atomicAdd(&g_cur[c], 1);
        float w = g_dinv[r] * g_dinv[c];
        g_csrw[g_off[c] + pos] = make_int2(r, __float_as_int(w));
    }
}

// ---------------- tf32 GEMM, templated input, fp16 output ----------------
__device__ __forceinline__ unsigned f2tf(float f) {
    unsigned u;
    asm("cvt.rna.tf32.f32 %0, %1;" : "=r"(u) : "f"(f));
    return u;
}
__device__ __forceinline__ float4 ld4(const float* p) { return *(const float4*)p; }
__device__ __forceinline__ float4 ld4(const __half* p) {
    uint2 r = *(const uint2*)p;
    float2 a = __half22float2(*(__half2*)&r.x);
    float2 b = __half22float2(*(__half2*)&r.y);
    return make_float4(a.x, a.y, b.x, b.y);
}

#define GEMM_SMEM (2 * 128 * 132 * 4)

template <typename T>
__global__ __launch_bounds__(256, 1) void k_gemm(const T* __restrict__ A,
                                                 const float* __restrict__ W,
                                                 __half* __restrict__ C, int M) {
    extern __shared__ unsigned smem[];
    unsigned* Ws = smem;              // [128][132]
    unsigned* As = smem + 128 * 132;  // [128][132]
    int tid = threadIdx.x;
    int m0 = blockIdx.x * 128;

#pragma unroll
    for (int j = 0; j < 16; j++) {
        int idx = tid + j * 256;
        int row = idx >> 5;
        int c4 = idx & 31;
        float4 v = ld4(W + row * 128 + c4 * 4);
        unsigned* p = &Ws[row * 132 + c4 * 4];
        p[0] = f2tf(v.x); p[1] = f2tf(v.y); p[2] = f2tf(v.z); p[3] = f2tf(v.w);
    }
#pragma unroll
    for (int j = 0; j < 16; j++) {
        int idx = tid + j * 256;
        int row = idx >> 5;
        int c4 = idx & 31;
        int gr = m0 + row;
        float4 v = (gr < M) ? ld4(A + (size_t)gr * 128 + c4 * 4)
                            : make_float4(0.f, 0.f, 0.f, 0.f);
        unsigned* p = &As[row * 132 + c4 * 4];
        p[0] = f2tf(v.x); p[1] = f2tf(v.y); p[2] = f2tf(v.z); p[3] = f2tf(v.w);
    }
    __syncthreads();

    int lane = tid & 31;
    int wid = tid >> 5;
    int g = lane >> 2;
    int tg = lane & 3;
    int wr = wid * 16;

    float acc[64];
#pragma unroll
    for (int i = 0; i < 64; i++) acc[i] = 0.f;

#pragma unroll
    for (int k0 = 0; k0 < 16; k0++) {
        int kk = k0 * 8;
        unsigned a0 = As[(wr + g) * 132 + kk + tg];
        unsigned a1 = As[(wr + g + 8) * 132 + kk + tg];
        unsigned a2 = As[(wr + g) * 132 + kk + tg + 4];
        unsigned a3 = As[(wr + g + 8) * 132 + kk + tg + 4];
        const unsigned* b0p = &Ws[(kk + tg) * 132 + g];
        const unsigned* b1p = &Ws[(kk + tg + 4) * 132 + g];
#pragma unroll
        for (int n0 = 0; n0 < 16; n0++) {
            unsigned b0 = b0p[n0 * 8];
            unsigned b1 = b1p[n0 * 8];
            float* c = &acc[n0 * 4];
            asm volatile(
                "mma.sync.aligned.m16n8k8.row.col.f32.tf32.tf32.f32 "
                "{%0,%1,%2,%3}, {%4,%5,%6,%7}, {%8,%9}, {%0,%1,%2,%3};"
                : "+f"(c[0]), "+f"(c[1]), "+f"(c[2]), "+f"(c[3])
                : "r"(a0), "r"(a1), "r"(a2), "r"(a3), "r"(b0), "r"(b1));
        }
    }

    int r0 = m0 + wr + g;
    int r1 = r0 + 8;
#pragma unroll
    for (int n0 = 0; n0 < 16; n0++) {
        int col = n0 * 8 + 2 * tg;
        if (r0 < M)
            *(__half2*)(C + (size_t)r0 * 128 + col) =
                __floats2half2_rn(acc[n0 * 4 + 0], acc[n0 * 4 + 1]);
        if (r1 < M)
            *(__half2*)(C + (size_t)r1 * 128 + col) =
                __floats2half2_rn(acc[n0 * 4 + 2], acc[n0 * 4 + 3]);
    }
}

// ---------------- aggregation: warp per dst, fp16 gather ----------------
__device__ __forceinline__ float4 h4f(uint2 r) {
    float2 a = __half22float2(*(__half2*)&r.x);
    float2 b = __half22float2(*(__half2*)&r.y);
    return make_float4(a.x, a.y, b.x, b.y);
}

__global__ void k_agg(const __half* __restrict__ hin, __half* __restrict__ hout,
                      const float* __restrict__ bias, int n) {
    int t = blockIdx.x * blockDim.x + threadIdx.x;
    int d = t >> 5;
    if (d >= n) return;
    int lane = t & 31;

    const uint2* h2 = (const uint2*)hin;   // 4 halves per lane
    float di = g_dinv[d];
    float4 sv = h4f(h2[(size_t)d * 32 + lane]);
    float ws = di * di;
    float4 acc = make_float4(ws * sv.x, ws * sv.y, ws * sv.z, ws * sv.w);

    int s0 = g_off[d];
    int e = g_deg[d] - 1;
    const int2* cp = g_csrw + s0;

    int i = 0;
    for (; i + 2 <= e; i += 2) {
        int2 e0 = cp[i];
        int2 e1 = cp[i + 1];
        uint2 r0 = h2[(size_t)e0.x * 32 + lane];
        uint2 r1 = h2[(size_t)e1.x * 32 + lane];
        float w0 = __int_as_float(e0.y);
        float w1 = __int_as_float(e1.y);
        float4 v0 = h4f(r0);
        float4 v1 = h4f(r1);
        acc.x += w0 * v0.x + w1 * v1.x;
        acc.y += w0 * v0.y + w1 * v1.y;
        acc.z += w0 * v0.z + w1 * v1.z;
        acc.w += w0 * v0.w + w1 * v1.w;
    }
    if (i < e) {
        int2 e0 = cp[i];
        float w0 = __int_as_float(e0.y);
        float4 v0 = h4f(h2[(size_t)e0.x * 32 + lane]);
        acc.x += w0 * v0.x; acc.y += w0 * v0.y;
        acc.z += w0 * v0.z; acc.w += w0 * v0.w;
    }

    float4 b = ((const float4*)bias)[lane];
    acc.x = fmaxf(acc.x + b.x, 0.f);
    acc.y = fmaxf(acc.y + b.y, 0.f);
    acc.z = fmaxf(acc.z + b.z, 0.f);
    acc.w = fmaxf(acc.w + b.w, 0.f);

    __half2 o0 = __floats2half2_rn(acc.x, acc.y);
    __half2 o1 = __floats2half2_rn(acc.z, acc.w);
    uint2 o;
    o.x = *(unsigned*)&o0;
    o.y = *(unsigned*)&o1;
    ((uint2*)hout)[(size_t)d * 32 + lane] = o;
}

// ---------------- graph scan ----------------
__global__ void k_gscan(int Gn) {
    __shared__ int sm[1024];
    int t = threadIdx.x;
    int v = (t < Gn) ? g_gcnt[t] : 0;
    sm[t] = v;
    __syncthreads();
    for (int ofs = 1; ofs < 1024; ofs <<= 1) {
        int tt = (t >= ofs) ? sm[t - ofs] : 0;
        __syncthreads();
        sm[t] += tt;
        __syncthreads();
    }
    if (t < Gn) g_goff[t] = sm[t] - v;
}

// ---------------- mean pool + head MLP ----------------
__global__ void k_pool(const float* __restrict__ u,
                       const float* __restrict__ Wh1, const float* __restrict__ bh1,
                       const float* __restrict__ Wh2, const float* __restrict__ bh2,
                       float* __restrict__ out) {
    __shared__ float hcat[192];
    __shared__ float mid[128];
    int g = blockIdx.x;
    int t = threadIdx.x;   // 128

    int start = g_goff[g];
    int cnt = g_gcnt[g];
    float acc = 0.f;
    for (int i = 0; i < cnt; i++)
        acc += __half2float(g_Hh[(size_t)(start + i) * 128 + t]);
    hcat[t] = acc / fmaxf((float)cnt, 1.f);
    if (t < 64) hcat[128 + t] = u[g * 64 + t];
    __syncthreads();

    float m = bh1[t];
#pragma unroll 4
    for (int k = 0; k < 192; k++) m += hcat[k] * Wh1[k * 128 + t];
    mid[t] = fmaxf(m, 0.f);
    __syncthreads();

    if (t < 2) {
        float o = bh2[t];
        for (int k = 0; k < 128; k++) o += mid[k] * Wh2[k * 2 + t];
        out[g * 2 + t] = o;
    }
}

// ---------------- launch ----------------
extern "C" void kernel_launch(void* const* d_in, const int* in_sizes, int n_in,
                              void* d_out, int out_size) {
    const float* x     = (const float*)d_in[0];
    const int*   ei    = (const int*)d_in[1];
    const float* u     = (const float*)d_in[2];
    const int*   batch = (const int*)d_in[3];
    int wi = (n_in >= 13) ? 5 : 4;
    const float* W1  = (const float*)d_in[wi + 0];
    const float* b1  = (const float*)d_in[wi + 1];
    const float* W2  = (const float*)d_in[wi + 2];
    const float* b2  = (const float*)d_in[wi + 3];
    const float* Wh1 = (const float*)d_in[wi + 4];
    const float* bh1 = (const float*)d_in[wi + 5];
    const float* Wh2 = (const float*)d_in[wi + 6];
    const float* bh2 = (const float*)d_in[wi + 7];
    float* out = (float*)d_out;

    int N = in_sizes[0] / D;
    int E = in_sizes[1] / 2;
    int G = in_sizes[2] / 64;

    void *pP, *pH;
    cudaGetSymbolAddress(&pP, g_Ph);
    cudaGetSymbolAddress(&pH, g_Hh);
    __half* P = (__half*)pP;
    __half* H = (__half*)pH;

    cudaFuncSetAttribute(k_gemm<float>,  cudaFuncAttributeMaxDynamicSharedMemorySize, GEMM_SMEM);
    cudaFuncSetAttribute(k_gemm<__half>, cudaFuncAttributeMaxDynamicSharedMemorySize, GEMM_SMEM);

    k_init<<<256, 256>>>(N, G);
    k_count<<<(E + 255) / 256, 256>>>(ei, E);
    k_gcount<<<(N + 255) / 256, 256>>>(batch, N);
    int nb = (N + 1023) / 1024;
    k_scanA<<<nb, 1024>>>(N);
    k_scanB<<<1, 256>>>(nb);
    k_scanC<<<nb, 1024>>>(N);
    k_fill<<<(E + 255) / 256, 256>>>(ei, E);
    k_gscan<<<1, 1024>>>(G);

    int mb = (N + 127) / 128;
    k_gemm<float><<<mb, 256, GEMM_SMEM>>>(x, W1, P, N);
    k_agg<<<(N * 32 + 255) / 256, 256>>>(P, H, b1, N);
    k_gemm<__half><<<mb, 256, GEMM_SMEM>>>(H, W2, P, N);
    k_agg<<<(N * 32 + 255) / 256, 256>>>(P, H, b2, N);

    k_pool<<<G, 128>>>(u, Wh1, bh1, Wh2, bh2, out);
}

// round 5
// speedup vs baseline: 1.1110x; 1.0106x over previous
#include <cuda_runtime.h>
#include <cuda_fp16.h>
#include <math.h>

#define NMAX 100000
#define EMAX 1600000
#define GMAX 1024
#define D    128

// ---------------- static device scratch ----------------
__device__ int    g_deg[NMAX];      // in-degree (edges only; self loop added in math)
__device__ float  g_dinv[NMAX];     // (deg+1)^-1/2
__device__ int    g_off[NMAX];      // block-local exclusive scan of deg
__device__ int    g_cur[NMAX];
__device__ int2   g_csrw[EMAX];     // {src, weight-as-int}
__device__ int    g_part[256];      // per-block scan partials (exclusive after scanB)
__device__ int    g_gcnt[GMAX];
__device__ int    g_goff[GMAX];
__device__ __half g_Ph[(size_t)NMAX * D];
__device__ __half g_Hh[(size_t)NMAX * D];

// ---------------- fused degree + graph count ----------------
__global__ void k_count(const int* __restrict__ ei, int E,
                        const int* __restrict__ batch, int N) {
    int i = blockIdx.x * blockDim.x + threadIdx.x;
    if (i < E) atomicAdd(&g_deg[ei[E + i]], 1);
    if (i < N) atomicAdd(&g_gcnt[batch[i]], 1);
}

// ---------------- scan of deg (block-local) + dinv ----------------
__global__ void k_scanA(int n) {
    __shared__ int sm[1024];
    int tid = threadIdx.x;
    int i = blockIdx.x * 1024 + tid;
    int v = 0;
    if (i < n) {
        int dg = g_deg[i];
        v = dg;
        g_dinv[i] = rsqrtf((float)(dg + 1));
    }
    sm[tid] = v;
    __syncthreads();
    for (int ofs = 1; ofs < 1024; ofs <<= 1) {
        int t = (tid >= ofs) ? sm[tid - ofs] : 0;
        __syncthreads();
        sm[tid] += t;
        __syncthreads();
    }
    if (i < n) g_off[i] = sm[tid] - v;           // block-local exclusive
    if (tid == 1023) g_part[blockIdx.x] = sm[tid];
}

// block 0: exclusive-scan the partials; block 1: graph-offset scan
__global__ void k_scanB(int nb, int Gn) {
    __shared__ int sm[1024];
    int t = threadIdx.x;
    if (blockIdx.x == 0) {
        int v = (t < nb) ? g_part[t] : 0;
        sm[t] = v;
        __syncthreads();
        for (int ofs = 1; ofs < 1024; ofs <<= 1) {
            int tt = (t >= ofs) ? sm[t - ofs] : 0;
            __syncthreads();
            sm[t] += tt;
            __syncthreads();
        }
        if (t < nb) g_part[t] = sm[t] - v;
    } else {
        int v = (t < Gn) ? g_gcnt[t] : 0;
        sm[t] = v;
        __syncthreads();
        for (int ofs = 1; ofs < 1024; ofs <<= 1) {
            int tt = (t >= ofs) ? sm[t - ofs] : 0;
            __syncthreads();
            sm[t] += tt;
            __syncthreads();
        }
        if (t < Gn) g_goff[t] = sm[t] - v;
    }
}

// ---------------- CSR fill (global offset folded in) ----------------
__global__ void k_fill(const int* __restrict__ ei, int E) {
    int e = blockIdx.x * blockDim.x + threadIdx.x;
    if (e < E) {
        int r = ei[e];
        int c = ei[E + e];
        int pos = atomicAdd(&g_cur[c], 1);
        float w = g_dinv[r] * g_dinv[c];
        g_csrw[g_off[c] + g_part[c >> 10] + pos] = make_int2(r, __float_as_int(w));
    }
}

// ---------------- tf32 GEMM, templated input, fp16 output ----------------
__device__ __forceinline__ unsigned f2tf(float f) {
    unsigned u;
    asm("cvt.rna.tf32.f32 %0, %1;" : "=r"(u) : "f"(f));
    return u;
}
__device__ __forceinline__ float4 ld4(const float* p) { return *(const float4*)p; }
__device__ __forceinline__ float4 ld4(const __half* p) {
    uint2 r = *(const uint2*)p;
    float2 a = __half22float2(*(__half2*)&r.x);
    float2 b = __half22float2(*(__half2*)&r.y);
    return make_float4(a.x, a.y, b.x, b.y);
}

#define GEMM_SMEM (2 * 128 * 132 * 4)

template <typename T>
__global__ __launch_bounds__(256, 1) void k_gemm(const T* __restrict__ A,
                                                 const float* __restrict__ W,
                                                 __half* __restrict__ C, int M) {
    extern __shared__ unsigned smem[];
    unsigned* Ws = smem;
    unsigned* As = smem + 128 * 132;
    int tid = threadIdx.x;
    int m0 = blockIdx.x * 128;

#pragma unroll
    for (int j = 0; j < 16; j++) {
        int idx = tid + j * 256;
        int row = idx >> 5;
        int c4 = idx & 31;
        float4 v = ld4(W + row * 128 + c4 * 4);
        unsigned* p = &Ws[row * 132 + c4 * 4];
        p[0] = f2tf(v.x); p[1] = f2tf(v.y); p[2] = f2tf(v.z); p[3] = f2tf(v.w);
    }
#pragma unroll
    for (int j = 0; j < 16; j++) {
        int idx = tid + j * 256;
        int row = idx >> 5;
        int c4 = idx & 31;
        int gr = m0 + row;
        float4 v = (gr < M) ? ld4(A + (size_t)gr * 128 + c4 * 4)
                            : make_float4(0.f, 0.f, 0.f, 0.f);
        unsigned* p = &As[row * 132 + c4 * 4];
        p[0] = f2tf(v.x); p[1] = f2tf(v.y); p[2] = f2tf(v.z); p[3] = f2tf(v.w);
    }
    __syncthreads();

    int lane = tid & 31;
    int wid = tid >> 5;
    int g = lane >> 2;
    int tg = lane & 3;
    int wr = wid * 16;

    float acc[64];
#pragma unroll
    for (int i = 0; i < 64; i++) acc[i] = 0.f;

#pragma unroll
    for (int k0 = 0; k0 < 16; k0++) {
        int kk = k0 * 8;
        unsigned a0 = As[(wr + g) * 132 + kk + tg];
        unsigned a1 = As[(wr + g + 8) * 132 + kk + tg];
        unsigned a2 = As[(wr + g) * 132 + kk + tg + 4];
        unsigned a3 = As[(wr + g + 8) * 132 + kk + tg + 4];
        const unsigned* b0p = &Ws[(kk + tg) * 132 + g];
        const unsigned* b1p = &Ws[(kk + tg + 4) * 132 + g];
#pragma unroll
        for (int n0 = 0; n0 < 16; n0++) {
            unsigned b0 = b0p[n0 * 8];
            unsigned b1 = b1p[n0 * 8];
            float* c = &acc[n0 * 4];
            asm volatile(
                "mma.sync.aligned.m16n8k8.row.col.f32.tf32.tf32.f32 "
                "{%0,%1,%2,%3}, {%4,%5,%6,%7}, {%8,%9}, {%0,%1,%2,%3};"
                : "+f"(c[0]), "+f"(c[1]), "+f"(c[2]), "+f"(c[3])
                : "r"(a0), "r"(a1), "r"(a2), "r"(a3), "r"(b0), "r"(b1));
        }
    }

    int r0 = m0 + wr + g;
    int r1 = r0 + 8;
#pragma unroll
    for (int n0 = 0; n0 < 16; n0++) {
        int col = n0 * 8 + 2 * tg;
        if (r0 < M)
            *(__half2*)(C + (size_t)r0 * 128 + col) =
                __floats2half2_rn(acc[n0 * 4 + 0], acc[n0 * 4 + 1]);
        if (r1 < M)
            *(__half2*)(C + (size_t)r1 * 128 + col) =
                __floats2half2_rn(acc[n0 * 4 + 2], acc[n0 * 4 + 3]);
    }
}

// ---------------- aggregation: warp per dst, half-warp-paired gather ----------------
// lanes 0-15 gather neighbor i (uint4 = 8 halves each, covering full 256B row),
// lanes 16-31 gather neighbor i+1; combine halves via shfl_xor(16) at the end.
__global__ void k_agg(const __half* __restrict__ hin, __half* __restrict__ hout,
                      const float* __restrict__ bias, int n) {
    int t = blockIdx.x * blockDim.x + threadIdx.x;
    int d = t >> 5;
    if (d >= n) return;
    int lane = t & 31;
    int hid = lane >> 4;     // half-warp id
    int sub = lane & 15;     // position within half-warp (channel chunk)

    const uint4* h4 = (const uint4*)hin;   // 16 uint4 per row
    float di = g_dinv[d];

    float acc[8];
#pragma unroll
    for (int k = 0; k < 8; k++) acc[k] = 0.f;

    // self loop: half 0 only
    if (hid == 0) {
        float ws = di * di;
        uint4 r = h4[(size_t)d * 16 + sub];
        float2 f0 = __half22float2(*(__half2*)&r.x);
        float2 f1 = __half22float2(*(__half2*)&r.y);
        float2 f2 = __half22float2(*(__half2*)&r.z);
        float2 f3 = __half22float2(*(__half2*)&r.w);
        acc[0] = ws * f0.x; acc[1] = ws * f0.y;
        acc[2] = ws * f1.x; acc[3] = ws * f1.y;
        acc[4] = ws * f2.x; acc[5] = ws * f2.y;
        acc[6] = ws * f3.x; acc[7] = ws * f3.y;
    }

    int e = g_deg[d];
    const int2* cp = g_csrw + g_off[d] + g_part[d >> 10];

    for (int i0 = 0; i0 < e; i0 += 2) {
        int i = i0 + hid;
        if (i < e) {
            int2 ew = cp[i];
            float w = __int_as_float(ew.y);
            uint4 r = h4[(size_t)ew.x * 16 + sub];
            float2 f0 = __half22float2(*(__half2*)&r.x);
            float2 f1 = __half22float2(*(__half2*)&r.y);
            float2 f2 = __half22float2(*(__half2*)&r.z);
            float2 f3 = __half22float2(*(__half2*)&r.w);
            acc[0] += w * f0.x; acc[1] += w * f0.y;
            acc[2] += w * f1.x; acc[3] += w * f1.y;
            acc[4] += w * f2.x; acc[5] += w * f2.y;
            acc[6] += w * f3.x; acc[7] += w * f3.y;
        }
    }

#pragma unroll
    for (int k = 0; k < 8; k++)
        acc[k] += __shfl_xor_sync(0xffffffffu, acc[k], 16);

    if (hid == 0) {
        float4 b0 = ((const float4*)bias)[sub * 2];
        float4 b1 = ((const float4*)bias)[sub * 2 + 1];
        acc[0] = fmaxf(acc[0] + b0.x, 0.f);
        acc[1] = fmaxf(acc[1] + b0.y, 0.f);
        acc[2] = fmaxf(acc[2] + b0.z, 0.f);
        acc[3] = fmaxf(acc[3] + b0.w, 0.f);
        acc[4] = fmaxf(acc[4] + b1.x, 0.f);
        acc[5] = fmaxf(acc[5] + b1.y, 0.f);
        acc[6] = fmaxf(acc[6] + b1.z, 0.f);
        acc[7] = fmaxf(acc[7] + b1.w, 0.f);
        __half2 o0 = __floats2half2_rn(acc[0], acc[1]);
        __half2 o1 = __floats2half2_rn(acc[2], acc[3]);
        __half2 o2 = __floats2half2_rn(acc[4], acc[5]);
        __half2 o3 = __floats2half2_rn(acc[6], acc[7]);
        uint4 o;
        o.x = *(unsigned*)&o0; o.y = *(unsigned*)&o1;
        o.z = *(unsigned*)&o2; o.w = *(unsigned*)&o3;
        ((uint4*)hout)[(size_t)d * 16 + sub] = o;
    }
}

// ---------------- mean pool + head MLP ----------------
__global__ void k_pool(const float* __restrict__ u,
                       const float* __restrict__ Wh1, const float* __restrict__ bh1,
                       const float* __restrict__ Wh2, const float* __restrict__ bh2,
                       float* __restrict__ out) {
    __shared__ float hcat[192];
    __shared__ float mid[128];
    int g = blockIdx.x;
    int t = threadIdx.x;   // 128

    int start = g_goff[g];
    int cnt = g_gcnt[g];
    float acc = 0.f;
    for (int i = 0; i < cnt; i++)
        acc += __half2float(g_Hh[(size_t)(start + i) * 128 + t]);
    hcat[t] = acc / fmaxf((float)cnt, 1.f);
    if (t < 64) hcat[128 + t] = u[g * 64 + t];
    __syncthreads();

    float m = bh1[t];
#pragma unroll 4
    for (int k = 0; k < 192; k++) m += hcat[k] * Wh1[k * 128 + t];
    mid[t] = fmaxf(m, 0.f);
    __syncthreads();

    if (t < 2) {
        float o = bh2[t];
        for (int k = 0; k < 128; k++) o += mid[k] * Wh2[k * 2 + t];
        out[g * 2 + t] = o;
    }
}

// ---------------- launch ----------------
extern "C" void kernel_launch(void* const* d_in, const int* in_sizes, int n_in,
                              void* d_out, int out_size) {
    const float* x     = (const float*)d_in[0];
    const int*   ei    = (const int*)d_in[1];
    const float* u     = (const float*)d_in[2];
    const int*   batch = (const int*)d_in[3];
    int wi = (n_in >= 13) ? 5 : 4;
    const float* W1  = (const float*)d_in[wi + 0];
    const float* b1  = (const float*)d_in[wi + 1];
    const float* W2  = (const float*)d_in[wi + 2];
    const float* b2  = (const float*)d_in[wi + 3];
    const float* Wh1 = (const float*)d_in[wi + 4];
    const float* bh1 = (const float*)d_in[wi + 5];
    const float* Wh2 = (const float*)d_in[wi + 6];
    const float* bh2 = (const float*)d_in[wi + 7];
    float* out = (float*)d_out;

    int N = in_sizes[0] / D;
    int E = in_sizes[1] / 2;
    int G = in_sizes[2] / 64;

    void *pP, *pH, *pDeg, *pCur, *pGc;
    cudaGetSymbolAddress(&pP, g_Ph);
    cudaGetSymbolAddress(&pH, g_Hh);
    cudaGetSymbolAddress(&pDeg, g_deg);
    cudaGetSymbolAddress(&pCur, g_cur);
    cudaGetSymbolAddress(&pGc, g_gcnt);
    __half* P = (__half*)pP;
    __half* H = (__half*)pH;

    cudaFuncSetAttribute(k_gemm<float>,  cudaFuncAttributeMaxDynamicSharedMemorySize, GEMM_SMEM);
    cudaFuncSetAttribute(k_gemm<__half>, cudaFuncAttributeMaxDynamicSharedMemorySize, GEMM_SMEM);

    cudaMemsetAsync(pDeg, 0, (size_t)N * sizeof(int), 0);
    cudaMemsetAsync(pCur, 0, (size_t)N * sizeof(int), 0);
    cudaMemsetAsync(pGc,  0, (size_t)G * sizeof(int), 0);

    k_count<<<(E + 255) / 256, 256>>>(ei, E, batch, N);
    int nb = (N + 1023) / 1024;
    k_scanA<<<nb, 1024>>>(N);
    k_scanB<<<2, 1024>>>(nb, G);
    k_fill<<<(E + 255) / 256, 256>>>(ei, E);

    int mb = (N + 127) / 128;
    k_gemm<float><<<mb, 256, GEMM_SMEM>>>(x, W1, P, N);
    k_agg<<<(N * 32 + 255) / 256, 256>>>(P, H, b1, N);
    k_gemm<__half><<<mb, 256, GEMM_SMEM>>>(H, W2, P, N);
    k_agg<<<(N * 32 + 255) / 256, 256>>>(P, H, b2, N);

    k_pool<<<G, 128>>>(u, Wh1, bh1, Wh2, bh2, out);
}

// round 6
// speedup vs baseline: 1.1747x; 1.0574x over previous
#include <cuda_runtime.h>
#include <cuda_fp16.h>
#include <math.h>

#define NMAX 100000
#define EMAX 1600000
#define GMAX 1024
#define D    128

// ---------------- static device scratch ----------------
__device__ int    g_deg[NMAX];      // in-degree (edges only)
__device__ float  g_dinv[NMAX];     // (deg+1)^-1/2
__device__ int    g_off[NMAX];      // block-local exclusive scan of deg
__device__ int    g_cur[NMAX];      // global start offset; fill cursor
__device__ int4   g_nd[NMAX];       // {start, deg, dinv-as-int, 0} packed per node
__device__ int2   g_csrw[EMAX];     // {src, weight-as-int}
__device__ int    g_part[256];
__device__ int    g_gcnt[GMAX];
__device__ int    g_goff[GMAX];
__device__ __half g_Ph[(size_t)NMAX * D];
__device__ __half g_Hh[(size_t)NMAX * D];

// ---------------- fused degree + graph count ----------------
__global__ void k_count(const int* __restrict__ ei, int E,
                        const int* __restrict__ batch, int N) {
    int i = blockIdx.x * blockDim.x + threadIdx.x;
    if (i < E) atomicAdd(&g_deg[ei[E + i]], 1);
    if (i < N) atomicAdd(&g_gcnt[batch[i]], 1);
}

// ---------------- scan of deg (block-local) + dinv ----------------
__global__ void k_scanA(int n) {
    __shared__ int sm[1024];
    int tid = threadIdx.x;
    int i = blockIdx.x * 1024 + tid;
    int v = 0;
    if (i < n) {
        int dg = g_deg[i];
        v = dg;
        g_dinv[i] = rsqrtf((float)(dg + 1));
    }
    sm[tid] = v;
    __syncthreads();
    for (int ofs = 1; ofs < 1024; ofs <<= 1) {
        int t = (tid >= ofs) ? sm[tid - ofs] : 0;
        __syncthreads();
        sm[tid] += t;
        __syncthreads();
    }
    if (i < n) g_off[i] = sm[tid] - v;
    if (tid == 1023) g_part[blockIdx.x] = sm[tid];
}

// block 0: exclusive-scan partials; block 1: graph-offset scan
__global__ void k_scanB(int nb, int Gn) {
    __shared__ int sm[1024];
    int t = threadIdx.x;
    if (blockIdx.x == 0) {
        int v = (t < nb) ? g_part[t] : 0;
        sm[t] = v;
        __syncthreads();
        for (int ofs = 1; ofs < 1024; ofs <<= 1) {
            int tt = (t >= ofs) ? sm[t - ofs] : 0;
            __syncthreads();
            sm[t] += tt;
            __syncthreads();
        }
        if (t < nb) g_part[t] = sm[t] - v;
    } else {
        int v = (t < Gn) ? g_gcnt[t] : 0;
        sm[t] = v;
        __syncthreads();
        for (int ofs = 1; ofs < 1024; ofs <<= 1) {
            int tt = (t >= ofs) ? sm[t - ofs] : 0;
            __syncthreads();
            sm[t] += tt;
            __syncthreads();
        }
        if (t < Gn) g_goff[t] = sm[t] - v;
    }
}

// ---------------- scanC: globalize offsets, pack node descriptor ----------------
__global__ void k_scanC(int n) {
    int i = blockIdx.x * 1024 + threadIdx.x;
    if (i < n) {
        int start = g_off[i] + g_part[i >> 10];
        g_cur[i] = start;                    // fill cursor starts at global base
        g_nd[i] = make_int4(start, g_deg[i], __float_as_int(g_dinv[i]), 0);
    }
}

// ---------------- CSR fill: cursor IS the slot ----------------
__global__ void k_fill(const int* __restrict__ ei, int E) {
    int e = blockIdx.x * blockDim.x + threadIdx.x;
    if (e < E) {
        int r = ei[e];
        int c = ei[E + e];
        int pos = atomicAdd(&g_cur[c], 1);
        float w = g_dinv[r] * g_dinv[c];
        g_csrw[pos] = make_int2(r, __float_as_int(w));
    }
}

// ---------------- tf32 GEMM, templated input, fp16 output ----------------
__device__ __forceinline__ unsigned f2tf(float f) {
    unsigned u;
    asm("cvt.rna.tf32.f32 %0, %1;" : "=r"(u) : "f"(f));
    return u;
}
__device__ __forceinline__ float4 ld4(const float* p) { return *(const float4*)p; }
__device__ __forceinline__ float4 ld4(const __half* p) {
    uint2 r = *(const uint2*)p;
    float2 a = __half22float2(*(__half2*)&r.x);
    float2 b = __half22float2(*(__half2*)&r.y);
    return make_float4(a.x, a.y, b.x, b.y);
}

#define GEMM_SMEM (2 * 128 * 132 * 4)

template <typename T>
__global__ __launch_bounds__(256, 1) void k_gemm(const T* __restrict__ A,
                                                 const float* __restrict__ W,
                                                 __half* __restrict__ C, int M) {
    extern __shared__ unsigned smem[];
    unsigned* Ws = smem;
    unsigned* As = smem + 128 * 132;
    int tid = threadIdx.x;
    int m0 = blockIdx.x * 128;

#pragma unroll
    for (int j = 0; j < 16; j++) {
        int idx = tid + j * 256;
        int row = idx >> 5;
        int c4 = idx & 31;
        float4 v = ld4(W + row * 128 + c4 * 4);
        unsigned* p = &Ws[row * 132 + c4 * 4];
        p[0] = f2tf(v.x); p[1] = f2tf(v.y); p[2] = f2tf(v.z); p[3] = f2tf(v.w);
    }
#pragma unroll
    for (int j = 0; j < 16; j++) {
        int idx = tid + j * 256;
        int row = idx >> 5;
        int c4 = idx & 31;
        int gr = m0 + row;
        float4 v = (gr < M) ? ld4(A + (size_t)gr * 128 + c4 * 4)
                            : make_float4(0.f, 0.f, 0.f, 0.f);
        unsigned* p = &As[row * 132 + c4 * 4];
        p[0] = f2tf(v.x); p[1] = f2tf(v.y); p[2] = f2tf(v.z); p[3] = f2tf(v.w);
    }
    __syncthreads();

    int lane = tid & 31;
    int wid = tid >> 5;
    int g = lane >> 2;
    int tg = lane & 3;
    int wr = wid * 16;

    float acc[64];
#pragma unroll
    for (int i = 0; i < 64; i++) acc[i] = 0.f;

#pragma unroll
    for (int k0 = 0; k0 < 16; k0++) {
        int kk = k0 * 8;
        unsigned a0 = As[(wr + g) * 132 + kk + tg];
        unsigned a1 = As[(wr + g + 8) * 132 + kk + tg];
        unsigned a2 = As[(wr + g) * 132 + kk + tg + 4];
        unsigned a3 = As[(wr + g + 8) * 132 + kk + tg + 4];
        const unsigned* b0p = &Ws[(kk + tg) * 132 + g];
        const unsigned* b1p = &Ws[(kk + tg + 4) * 132 + g];
#pragma unroll
        for (int n0 = 0; n0 < 16; n0++) {
            unsigned b0 = b0p[n0 * 8];
            unsigned b1 = b1p[n0 * 8];
            float* c = &acc[n0 * 4];
            asm volatile(
                "mma.sync.aligned.m16n8k8.row.col.f32.tf32.tf32.f32 "
                "{%0,%1,%2,%3}, {%4,%5,%6,%7}, {%8,%9}, {%0,%1,%2,%3};"
                : "+f"(c[0]), "+f"(c[1]), "+f"(c[2]), "+f"(c[3])
                : "r"(a0), "r"(a1), "r"(a2), "r"(a3), "r"(b0), "r"(b1));
        }
    }

    int r0 = m0 + wr + g;
    int r1 = r0 + 8;
#pragma unroll
    for (int n0 = 0; n0 < 16; n0++) {
        int col = n0 * 8 + 2 * tg;
        if (r0 < M)
            *(__half2*)(C + (size_t)r0 * 128 + col) =
                __floats2half2_rn(acc[n0 * 4 + 0], acc[n0 * 4 + 1]);
        if (r1 < M)
            *(__half2*)(C + (size_t)r1 * 128 + col) =
                __floats2half2_rn(acc[n0 * 4 + 2], acc[n0 * 4 + 3]);
    }
}

// ---------------- aggregation: warp per dst, 4 neighbors / iteration ----------------
__global__ void k_agg(const __half* __restrict__ hin, __half* __restrict__ hout,
                      const float* __restrict__ bias, int n) {
    int t = blockIdx.x * blockDim.x + threadIdx.x;
    int d = t >> 5;
    if (d >= n) return;
    int lane = t & 31;
    int hid = lane >> 4;     // half-warp id
    int sub = lane & 15;     // channel chunk within half-warp

    const uint4* h4 = (const uint4*)hin;   // 16 uint4 per 128-half row

    int4 nd = g_nd[d];
    int start = nd.x;
    int e = nd.y;
    float di = __int_as_float(nd.z);

    float acc[8];
#pragma unroll
    for (int k = 0; k < 8; k++) acc[k] = 0.f;

    // self loop: half 0 only
    if (hid == 0) {
        float ws = di * di;
        uint4 r = h4[(size_t)d * 16 + sub];
        float2 f0 = __half22float2(*(__half2*)&r.x);
        float2 f1 = __half22float2(*(__half2*)&r.y);
        float2 f2 = __half22float2(*(__half2*)&r.z);
        float2 f3 = __half22float2(*(__half2*)&r.w);
        acc[0] = ws * f0.x; acc[1] = ws * f0.y;
        acc[2] = ws * f1.x; acc[3] = ws * f1.y;
        acc[4] = ws * f2.x; acc[5] = ws * f2.y;
        acc[6] = ws * f3.x; acc[7] = ws * f3.y;
    }

    const int2* cp = g_csrw + start;

    int i0 = 0;
    // main: 4 edges per warp-iteration, 2 per half-warp (2 row loads in flight per lane)
    for (; i0 + 4 <= e; i0 += 4) {
        int i = i0 + hid * 2;
        int2 ea = cp[i];
        int2 eb = cp[i + 1];
        uint4 ra = h4[(size_t)ea.x * 16 + sub];
        uint4 rb = h4[(size_t)eb.x * 16 + sub];
        float wa = __int_as_float(ea.y);
        float wb = __int_as_float(eb.y);
        {
            float2 f0 = __half22float2(*(__half2*)&ra.x);
            float2 f1 = __half22float2(*(__half2*)&ra.y);
            float2 f2 = __half22float2(*(__half2*)&ra.z);
            float2 f3 = __half22float2(*(__half2*)&ra.w);
            acc[0] += wa * f0.x; acc[1] += wa * f0.y;
            acc[2] += wa * f1.x; acc[3] += wa * f1.y;
            acc[4] += wa * f2.x; acc[5] += wa * f2.y;
            acc[6] += wa * f3.x; acc[7] += wa * f3.y;
        }
        {
            float2 f0 = __half22float2(*(__half2*)&rb.x);
            float2 f1 = __half22float2(*(__half2*)&rb.y);
            float2 f2 = __half22float2(*(__half2*)&rb.z);
            float2 f3 = __half22float2(*(__half2*)&rb.w);
            acc[0] += wb * f0.x; acc[1] += wb * f0.y;
            acc[2] += wb * f1.x; acc[3] += wb * f1.y;
            acc[4] += wb * f2.x; acc[5] += wb * f2.y;
            acc[6] += wb * f3.x; acc[7] += wb * f3.y;
        }
    }
    // remainder: paired, 2 edges per iteration
    for (; i0 < e; i0 += 2) {
        int i = i0 + hid;
        if (i < e) {
            int2 ew = cp[i];
            float w = __int_as_float(ew.y);
            uint4 r = h4[(size_t)ew.x * 16 + sub];
            float2 f0 = __half22float2(*(__half2*)&r.x);
            float2 f1 = __half22float2(*(__half2*)&r.y);
            float2 f2 = __half22float2(*(__half2*)&r.z);
            float2 f3 = __half22float2(*(__half2*)&r.w);
            acc[0] += w * f0.x; acc[1] += w * f0.y;
            acc[2] += w * f1.x; acc[3] += w * f1.y;
            acc[4] += w * f2.x; acc[5] += w * f2.y;
            acc[6] += w * f3.x; acc[7] += w * f3.y;
        }
    }

#pragma unroll
    for (int k = 0; k < 8; k++)
        acc[k] += __shfl_xor_sync(0xffffffffu, acc[k], 16);

    if (hid == 0) {
        float4 b0 = ((const float4*)bias)[sub * 2];
        float4 b1 = ((const float4*)bias)[sub * 2 + 1];
        acc[0] = fmaxf(acc[0] + b0.x, 0.f);
        acc[1] = fmaxf(acc[1] + b0.y, 0.f);
        acc[2] = fmaxf(acc[2] + b0.z, 0.f);
        acc[3] = fmaxf(acc[3] + b0.w, 0.f);
        acc[4] = fmaxf(acc[4] + b1.x, 0.f);
        acc[5] = fmaxf(acc[5] + b1.y, 0.f);
        acc[6] = fmaxf(acc[6] + b1.z, 0.f);
        acc[7] = fmaxf(acc[7] + b1.w, 0.f);
        __half2 o0 = __floats2half2_rn(acc[0], acc[1]);
        __half2 o1 = __floats2half2_rn(acc[2], acc[3]);
        __half2 o2 = __floats2half2_rn(acc[4], acc[5]);
        __half2 o3 = __floats2half2_rn(acc[6], acc[7]);
        uint4 o;
        o.x = *(unsigned*)&o0; o.y = *(unsigned*)&o1;
        o.z = *(unsigned*)&o2; o.w = *(unsigned*)&o3;
        ((uint4*)hout)[(size_t)d * 16 + sub] = o;
    }
}

// ---------------- mean pool + head MLP ----------------
__global__ void k_pool(const float* __restrict__ u,
                       const float* __restrict__ Wh1, const float* __restrict__ bh1,
                       const float* __restrict__ Wh2, const float* __restrict__ bh2,
                       float* __restrict__ out) {
    __shared__ float hcat[192];
    __shared__ float mid[128];
    int g = blockIdx.x;
    int t = threadIdx.x;   // 128

    int start = g_goff[g];
    int cnt = g_gcnt[g];
    float acc = 0.f;
    for (int i = 0; i < cnt; i++)
        acc += __half2float(g_Hh[(size_t)(start + i) * 128 + t]);
    hcat[t] = acc / fmaxf((float)cnt, 1.f);
    if (t < 64) hcat[128 + t] = u[g * 64 + t];
    __syncthreads();

    float m = bh1[t];
#pragma unroll 4
    for (int k = 0; k < 192; k++) m += hcat[k] * Wh1[k * 128 + t];
    mid[t] = fmaxf(m, 0.f);
    __syncthreads();

    if (t < 2) {
        float o = bh2[t];
        for (int k = 0; k < 128; k++) o += mid[k] * Wh2[k * 2 + t];
        out[g * 2 + t] = o;
    }
}

// ---------------- launch ----------------
extern "C" void kernel_launch(void* const* d_in, const int* in_sizes, int n_in,
                              void* d_out, int out_size) {
    const float* x     = (const float*)d_in[0];
    const int*   ei    = (const int*)d_in[1];
    const float* u     = (const float*)d_in[2];
    const int*   batch = (const int*)d_in[3];
    int wi = (n_in >= 13) ? 5 : 4;
    const float* W1  = (const float*)d_in[wi + 0];
    const float* b1  = (const float*)d_in[wi + 1];
    const float* W2  = (const float*)d_in[wi + 2];
    const float* b2  = (const float*)d_in[wi + 3];
    const float* Wh1 = (const float*)d_in[wi + 4];
    const float* bh1 = (const float*)d_in[wi + 5];
    const float* Wh2 = (const float*)d_in[wi + 6];
    const float* bh2 = (const float*)d_in[wi + 7];
    float* out = (float*)d_out;

    int N = in_sizes[0] / D;
    int E = in_sizes[1] / 2;
    int G = in_sizes[2] / 64;

    void *pP, *pH, *pDeg, *pGc;
    cudaGetSymbolAddress(&pP, g_Ph);
    cudaGetSymbolAddress(&pH, g_Hh);
    cudaGetSymbolAddress(&pDeg, g_deg);
    cudaGetSymbolAddress(&pGc, g_gcnt);
    __half* P = (__half*)pP;
    __half* H = (__half*)pH;

    cudaFuncSetAttribute(k_gemm<float>,  cudaFuncAttributeMaxDynamicSharedMemorySize, GEMM_SMEM);
    cudaFuncSetAttribute(k_gemm<__half>, cudaFuncAttributeMaxDynamicSharedMemorySize, GEMM_SMEM);

    cudaMemsetAsync(pDeg, 0, (size_t)N * sizeof(int), 0);
    cudaMemsetAsync(pGc,  0, (size_t)G * sizeof(int), 0);

    k_count<<<(E + 255) / 256, 256>>>(ei, E, batch, N);
    int nb = (N + 1023) / 1024;
    k_scanA<<<nb, 1024>>>(N);
    k_scanB<<<2, 1024>>>(nb, G);
    k_scanC<<<nb, 1024>>>(N);
    k_fill<<<(E + 255) / 256, 256>>>(ei, E);

    int mb = (N + 127) / 128;
    k_gemm<float><<<mb, 256, GEMM_SMEM>>>(x, W1, P, N);
    k_agg<<<(N * 32 + 255) / 256, 256>>>(P, H, b1, N);
    k_gemm<__half><<<mb, 256, GEMM_SMEM>>>(H, W2, P, N);
    k_agg<<<(N * 32 + 255) / 256, 256>>>(P, H, b2, N);

    k_pool<<<G, 128>>>(u, Wh1, bh1, Wh2, bh2, out);
}

// round 11
// speedup vs baseline: 1.1751x; 1.0003x over previous
#include <cuda_runtime.h>
#include <cuda_fp16.h>
#include <math.h>

#define NMAX 100000
#define EMAX 1600000
#define GMAX 1024
#define D    128

// ---------------- static device scratch ----------------
__device__ int    g_deg[NMAX];      // in-degree (edges only)
__device__ float  g_dinv[NMAX];     // (deg+1)^-1/2
__device__ int    g_off[NMAX];      // block-local exclusive scan of deg
__device__ int    g_cur[NMAX];      // global start offset; fill cursor
__device__ int4   g_nd[NMAX];       // {start, deg, dinv-as-int, 0}
__device__ int2   g_csrw[EMAX];     // {src, dinv_src-as-int}
__device__ int    g_part[256];
__device__ int    g_gcnt[GMAX];
__device__ int    g_goff[GMAX];
__device__ __half g_Ph[(size_t)NMAX * D];
__device__ __half g_Hh[(size_t)NMAX * D];

// ---------------- fused degree + graph count ----------------
__global__ void k_count(const int* __restrict__ ei, int E,
                        const int* __restrict__ batch, int N) {
    int i = blockIdx.x * blockDim.x + threadIdx.x;
    if (i < E) atomicAdd(&g_deg[ei[E + i]], 1);
    if (i < N) atomicAdd(&g_gcnt[batch[i]], 1);
}

// ---------------- scan of deg (block-local) + dinv ----------------
__global__ void k_scanA(int n) {
    __shared__ int sm[1024];
    int tid = threadIdx.x;
    int i = blockIdx.x * 1024 + tid;
    int v = 0;
    if (i < n) {
        int dg = g_deg[i];
        v = dg;
        g_dinv[i] = rsqrtf((float)(dg + 1));
    }
    sm[tid] = v;
    __syncthreads();
    for (int ofs = 1; ofs < 1024; ofs <<= 1) {
        int t = (tid >= ofs) ? sm[tid - ofs] : 0;
        __syncthreads();
        sm[tid] += t;
        __syncthreads();
    }
    if (i < n) g_off[i] = sm[tid] - v;
    if (tid == 1023) g_part[blockIdx.x] = sm[tid];
}

// block 0: exclusive-scan partials; block 1: graph-offset scan
__global__ void k_scanB(int nb, int Gn) {
    __shared__ int sm[1024];
    int t = threadIdx.x;
    if (blockIdx.x == 0) {
        int v = (t < nb) ? g_part[t] : 0;
        sm[t] = v;
        __syncthreads();
        for (int ofs = 1; ofs < 1024; ofs <<= 1) {
            int tt = (t >= ofs) ? sm[t - ofs] : 0;
            __syncthreads();
            sm[t] += tt;
            __syncthreads();
        }
        if (t < nb) g_part[t] = sm[t] - v;
    } else {
        int v = (t < Gn) ? g_gcnt[t] : 0;
        sm[t] = v;
        __syncthreads();
        for (int ofs = 1; ofs < 1024; ofs <<= 1) {
            int tt = (t >= ofs) ? sm[t - ofs] : 0;
            __syncthreads();
            sm[t] += tt;
            __syncthreads();
        }
        if (t < Gn) g_goff[t] = sm[t] - v;
    }
}

// ---------------- scanC: globalize offsets, pack node descriptor ----------------
__global__ void k_scanC(int n) {
    int i = blockIdx.x * 1024 + threadIdx.x;
    if (i < n) {
        int start = g_off[i] + g_part[i >> 10];
        g_cur[i] = start;
        g_nd[i] = make_int4(start, g_deg[i], __float_as_int(g_dinv[i]), 0);
    }
}

// ---------------- CSR fill: store {src, dinv_src}; dst scale applied in agg ----------------
__global__ void k_fill(const int* __restrict__ ei, int E) {
    int e = blockIdx.x * blockDim.x + threadIdx.x;
    if (e < E) {
        int r = ei[e];
        int c = ei[E + e];
        int pos = atomicAdd(&g_cur[c], 1);
        g_csrw[pos] = make_int2(r, __float_as_int(g_dinv[r]));
    }
}

// ---------------- tf32 GEMM, templated input, fp16 output ----------------
__device__ __forceinline__ unsigned f2tf(float f) {
    unsigned u;
    asm("cvt.rna.tf32.f32 %0, %1;" : "=r"(u) : "f"(f));
    return u;
}
__device__ __forceinline__ float4 ld4(const float* p) { return *(const float4*)p; }
__device__ __forceinline__ float4 ld4(const __half* p) {
    uint2 r = *(const uint2*)p;
    float2 a = __half22float2(*(__half2*)&r.x);
    float2 b = __half22float2(*(__half2*)&r.y);
    return make_float4(a.x, a.y, b.x, b.y);
}

#define GEMM_SMEM (2 * 128 * 132 * 4)

template <typename T>
__global__ __launch_bounds__(256, 1) void k_gemm(const T* __restrict__ A,
                                                 const float* __restrict__ W,
                                                 __half* __restrict__ C, int M) {
    extern __shared__ unsigned smem[];
    unsigned* Ws = smem;
    unsigned* As = smem + 128 * 132;
    int tid = threadIdx.x;
    int m0 = blockIdx.x * 128;

#pragma unroll
    for (int j = 0; j < 16; j++) {
        int idx = tid + j * 256;
        int row = idx >> 5;
        int c4 = idx & 31;
        float4 v = ld4(W + row * 128 + c4 * 4);
        unsigned* p = &Ws[row * 132 + c4 * 4];
        p[0] = f2tf(v.x); p[1] = f2tf(v.y); p[2] = f2tf(v.z); p[3] = f2tf(v.w);
    }
#pragma unroll
    for (int j = 0; j < 16; j++) {
        int idx = tid + j * 256;
        int row = idx >> 5;
        int c4 = idx & 31;
        int gr = m0 + row;
        float4 v = (gr < M) ? ld4(A + (size_t)gr * 128 + c4 * 4)
                            : make_float4(0.f, 0.f, 0.f, 0.f);
        unsigned* p = &As[row * 132 + c4 * 4];
        p[0] = f2tf(v.x); p[1] = f2tf(v.y); p[2] = f2tf(v.z); p[3] = f2tf(v.w);
    }
    __syncthreads();

    int lane = tid & 31;
    int wid = tid >> 5;
    int g = lane >> 2;
    int tg = lane & 3;
    int wr = wid * 16;

    float acc[64];
#pragma unroll
    for (int i = 0; i < 64; i++) acc[i] = 0.f;

#pragma unroll
    for (int k0 = 0; k0 < 16; k0++) {
        int kk = k0 * 8;
        unsigned a0 = As[(wr + g) * 132 + kk + tg];
        unsigned a1 = As[(wr + g + 8) * 132 + kk + tg];
        unsigned a2 = As[(wr + g) * 132 + kk + tg + 4];
        unsigned a3 = As[(wr + g + 8) * 132 + kk + tg + 4];
        const unsigned* b0p = &Ws[(kk + tg) * 132 + g];
        const unsigned* b1p = &Ws[(kk + tg + 4) * 132 + g];
#pragma unroll
        for (int n0 = 0; n0 < 16; n0++) {
            unsigned b0 = b0p[n0 * 8];
            unsigned b1 = b1p[n0 * 8];
            float* c = &acc[n0 * 4];
            asm volatile(
                "mma.sync.aligned.m16n8k8.row.col.f32.tf32.tf32.f32 "
                "{%0,%1,%2,%3}, {%4,%5,%6,%7}, {%8,%9}, {%0,%1,%2,%3};"
                : "+f"(c[0]), "+f"(c[1]), "+f"(c[2]), "+f"(c[3])
                : "r"(a0), "r"(a1), "r"(a2), "r"(a3), "r"(b0), "r"(b1));
        }
    }

    int r0 = m0 + wr + g;
    int r1 = r0 + 8;
#pragma unroll
    for (int n0 = 0; n0 < 16; n0++) {
        int col = n0 * 8 + 2 * tg;
        if (r0 < M)
            *(__half2*)(C + (size_t)r0 * 128 + col) =
                __floats2half2_rn(acc[n0 * 4 + 0], acc[n0 * 4 + 1]);
        if (r1 < M)
            *(__half2*)(C + (size_t)r1 * 128 + col) =
                __floats2half2_rn(acc[n0 * 4 + 2], acc[n0 * 4 + 3]);
    }
}

// ---------------- aggregation: warp per dst, 8 edges / warp-iteration ----------------
__device__ __forceinline__ void acc_row(float* acc, uint4 r, float w) {
    float2 f0 = __half22float2(*(__half2*)&r.x);
    float2 f1 = __half22float2(*(__half2*)&r.y);
    float2 f2 = __half22float2(*(__half2*)&r.z);
    float2 f3 = __half22float2(*(__half2*)&r.w);
    acc[0] += w * f0.x; acc[1] += w * f0.y;
    acc[2] += w * f1.x; acc[3] += w * f1.y;
    acc[4] += w * f2.x; acc[5] += w * f2.y;
    acc[6] += w * f3.x; acc[7] += w * f3.y;
}

__global__ void k_agg(const __half* __restrict__ hin, __half* __restrict__ hout,
                      const float* __restrict__ bias, int n) {
    int t = blockIdx.x * blockDim.x + threadIdx.x;
    int d = t >> 5;
    if (d >= n) return;
    int lane = t & 31;
    int hid = lane >> 4;
    int sub = lane & 15;

    const uint4* h4 = (const uint4*)hin;

    int4 nd = g_nd[d];
    int start = nd.x;
    int e = nd.y;
    float di = __int_as_float(nd.z);

    float acc[8];
#pragma unroll
    for (int k = 0; k < 8; k++) acc[k] = 0.f;

    // self loop with weight di (epilogue multiplies everything by di -> di^2)
    if (hid == 0) {
        uint4 r = h4[(size_t)d * 16 + sub];
        acc_row(acc, r, di);
    }

    const int2* cp = g_csrw + start;

    int i0 = 0;
    // main: 8 edges per warp-iteration, 4 per half-warp (4 rows in flight/lane)
    for (; i0 + 8 <= e; i0 += 8) {
        int i = i0 + hid * 4;
        int2 ea = cp[i];
        int2 eb = cp[i + 1];
        int2 ec = cp[i + 2];
        int2 ed = cp[i + 3];
        uint4 ra = h4[(size_t)ea.x * 16 + sub];
        uint4 rb = h4[(size_t)eb.x * 16 + sub];
        uint4 rc = h4[(size_t)ec.x * 16 + sub];
        uint4 rd = h4[(size_t)ed.x * 16 + sub];
        acc_row(acc, ra, __int_as_float(ea.y));
        acc_row(acc, rb, __int_as_float(eb.y));
        acc_row(acc, rc, __int_as_float(ec.y));
        acc_row(acc, rd, __int_as_float(ed.y));
    }
    // remainder: 2 per iteration
    for (; i0 < e; i0 += 2) {
        int i = i0 + hid;
        if (i < e) {
            int2 ew = cp[i];
            uint4 r = h4[(size_t)ew.x * 16 + sub];
            acc_row(acc, r, __int_as_float(ew.y));
        }
    }

#pragma unroll
    for (int k = 0; k < 8; k++)
        acc[k] += __shfl_xor_sync(0xffffffffu, acc[k], 16);

    if (hid == 0) {
        float4 b0 = ((const float4*)bias)[sub * 2];
        float4 b1 = ((const float4*)bias)[sub * 2 + 1];
        acc[0] = fmaxf(di * acc[0] + b0.x, 0.f);
        acc[1] = fmaxf(di * acc[1] + b0.y, 0.f);
        acc[2] = fmaxf(di * acc[2] + b0.z, 0.f);
        acc[3] = fmaxf(di * acc[3] + b0.w, 0.f);
        acc[4] = fmaxf(di * acc[4] + b1.x, 0.f);
        acc[5] = fmaxf(di * acc[5] + b1.y, 0.f);
        acc[6] = fmaxf(di * acc[6] + b1.z, 0.f);
        acc[7] = fmaxf(di * acc[7] + b1.w, 0.f);
        __half2 o0 = __floats2half2_rn(acc[0], acc[1]);
        __half2 o1 = __floats2half2_rn(acc[2], acc[3]);
        __half2 o2 = __floats2half2_rn(acc[4], acc[5]);
        __half2 o3 = __floats2half2_rn(acc[6], acc[7]);
        uint4 o;
        o.x = *(unsigned*)&o0; o.y = *(unsigned*)&o1;
        o.z = *(unsigned*)&o2; o.w = *(unsigned*)&o3;
        ((uint4*)hout)[(size_t)d * 16 + sub] = o;
    }
}

// ---------------- mean pool + head MLP ----------------
__global__ void k_pool(const float* __restrict__ u,
                       const float* __restrict__ Wh1, const float* __restrict__ bh1,
                       const float* __restrict__ Wh2, const float* __restrict__ bh2,
                       float* __restrict__ out) {
    __shared__ float hcat[192];
    __shared__ float mid[128];
    int g = blockIdx.x;
    int t = threadIdx.x;   // 128

    int start = g_goff[g];
    int cnt = g_gcnt[g];
    float acc = 0.f;
    for (int i = 0; i < cnt; i++)
        acc += __half2float(g_Hh[(size_t)(start + i) * 128 + t]);
    hcat[t] = acc / fmaxf((float)cnt, 1.f);
    if (t < 64) hcat[128 + t] = u[g * 64 + t];
    __syncthreads();

    float m = bh1[t];
#pragma unroll 4
    for (int k = 0; k < 192; k++) m += hcat[k] * Wh1[k * 128 + t];
    mid[t] = fmaxf(m, 0.f);
    __syncthreads();

    if (t < 2) {
        float o = bh2[t];
        for (int k = 0; k < 128; k++) o += mid[k] * Wh2[k * 2 + t];
        out[g * 2 + t] = o;
    }
}

// ---------------- launch ----------------
extern "C" void kernel_launch(void* const* d_in, const int* in_sizes, int n_in,
                              void* d_out, int out_size) {
    const float* x     = (const float*)d_in[0];
    const int*   ei    = (const int*)d_in[1];
    const float* u     = (const float*)d_in[2];
    const int*   batch = (const int*)d_in[3];
    int wi = (n_in >= 13) ? 5 : 4;
    const float* W1  = (const float*)d_in[wi + 0];
    const float* b1  = (const float*)d_in[wi + 1];
    const float* W2  = (const float*)d_in[wi + 2];
    const float* b2  = (const float*)d_in[wi + 3];
    const float* Wh1 = (const float*)d_in[wi + 4];
    const float* bh1 = (const float*)d_in[wi + 5];
    const float* Wh2 = (const float*)d_in[wi + 6];
    const float* bh2 = (const float*)d_in[wi + 7];
    float* out = (float*)d_out;

    int N = in_sizes[0] / D;
    int E = in_sizes[1] / 2;
    int G = in_sizes[2] / 64;

    void *pP, *pH, *pDeg, *pGc;
    cudaGetSymbolAddress(&pP, g_Ph);
    cudaGetSymbolAddress(&pH, g_Hh);
    cudaGetSymbolAddress(&pDeg, g_deg);
    cudaGetSymbolAddress(&pGc, g_gcnt);
    __half* P = (__half*)pP;
    __half* H = (__half*)pH;

    cudaFuncSetAttribute(k_gemm<float>,  cudaFuncAttributeMaxDynamicSharedMemorySize, GEMM_SMEM);
    cudaFuncSetAttribute(k_gemm<__half>, cudaFuncAttributeMaxDynamicSharedMemorySize, GEMM_SMEM);

    cudaMemsetAsync(pDeg, 0, (size_t)N * sizeof(int), 0);
    cudaMemsetAsync(pGc,  0, (size_t)G * sizeof(int), 0);

    k_count<<<(E + 255) / 256, 256>>>(ei, E, batch, N);
    int nb = (N + 1023) / 1024;
    k_scanA<<<nb, 1024>>>(N);
    k_scanB<<<2, 1024>>>(nb, G);
    k_scanC<<<nb, 1024>>>(N);
    k_fill<<<(E + 255) / 256, 256>>>(ei, E);

    int mb = (N + 127) / 128;
    k_gemm<float><<<mb, 256, GEMM_SMEM>>>(x, W1, P, N);
    k_agg<<<(N * 32 + 255) / 256, 256>>>(P, H, b1, N);
    k_gemm<__half><<<mb, 256, GEMM_SMEM>>>(H, W2, P, N);
    k_agg<<<(N * 32 + 255) / 256, 256>>>(P, H, b2, N);

    k_pool<<<G, 128>>>(u, Wh1, bh1, Wh2, bh2, out);
}

// round 16
// speedup vs baseline: 1.2550x; 1.0680x over previous
#include <cuda_runtime.h>
#include <cuda_fp16.h>
#include <math.h>

#define NMAX 100000
#define EMAX 1600000
#define GMAX 1024
#define D    128

// ---------------- static device scratch ----------------
__device__ int    g_cnts[NMAX + GMAX]; // [0,NMAX): in-degree, [NMAX,+GMAX): graph counts
__device__ float  g_dinv[NMAX];        // (deg+1)^-1/2
__device__ int    g_off[NMAX];         // block-local exclusive scan of deg
__device__ int    g_cur[NMAX];         // global start offset; fill cursor
__device__ int4   g_nd[NMAX];          // {start, deg, dinv-as-int, 0}
__device__ int2   g_csrw[EMAX];        // {src, dinv_src-as-int}
__device__ int    g_part[256];
__device__ int    g_goff[GMAX];
__device__ __half g_Ph[(size_t)NMAX * D];
__device__ __half g_Hh[(size_t)NMAX * D];

// ---------------- fused degree + graph count ----------------
__global__ void k_count(const int* __restrict__ ei, int E,
                        const int* __restrict__ batch, int N) {
    int i = blockIdx.x * blockDim.x + threadIdx.x;
    if (i < E) atomicAdd(&g_cnts[ei[E + i]], 1);
    if (i < N) atomicAdd(&g_cnts[NMAX + batch[i]], 1);
}

// ---------------- scan of deg (block-local) + dinv ----------------
__global__ void k_scanA(int n) {
    __shared__ int sm[1024];
    int tid = threadIdx.x;
    int i = blockIdx.x * 1024 + tid;
    int v = 0;
    if (i < n) {
        int dg = g_cnts[i];
        v = dg;
        g_dinv[i] = rsqrtf((float)(dg + 1));
    }
    sm[tid] = v;
    __syncthreads();
    for (int ofs = 1; ofs < 1024; ofs <<= 1) {
        int t = (tid >= ofs) ? sm[tid - ofs] : 0;
        __syncthreads();
        sm[tid] += t;
        __syncthreads();
    }
    if (i < n) g_off[i] = sm[tid] - v;
    if (tid == 1023) g_part[blockIdx.x] = sm[tid];
}

// block 0: exclusive-scan partials; block 1: graph-offset scan
__global__ void k_scanB(int nb, int Gn) {
    __shared__ int sm[1024];
    int t = threadIdx.x;
    if (blockIdx.x == 0) {
        int v = (t < nb) ? g_part[t] : 0;
        sm[t] = v;
        __syncthreads();
        for (int ofs = 1; ofs < 1024; ofs <<= 1) {
            int tt = (t >= ofs) ? sm[t - ofs] : 0;
            __syncthreads();
            sm[t] += tt;
            __syncthreads();
        }
        if (t < nb) g_part[t] = sm[t] - v;
    } else {
        int v = (t < Gn) ? g_cnts[NMAX + t] : 0;
        sm[t] = v;
        __syncthreads();
        for (int ofs = 1; ofs < 1024; ofs <<= 1) {
            int tt = (t >= ofs) ? sm[t - ofs] : 0;
            __syncthreads();
            sm[t] += tt;
            __syncthreads();
        }
        if (t < Gn) g_goff[t] = sm[t] - v;
    }
}

// ---------------- scanC: globalize offsets, pack node descriptor ----------------
__global__ void k_scanC(int n) {
    int i = blockIdx.x * 1024 + threadIdx.x;
    if (i < n) {
        int start = g_off[i] + g_part[i >> 10];
        g_cur[i] = start;
        g_nd[i] = make_int4(start, g_cnts[i], __float_as_int(g_dinv[i]), 0);
    }
}

// ---------------- CSR fill ----------------
__global__ void k_fill(const int* __restrict__ ei, int E) {
    int e = blockIdx.x * blockDim.x + threadIdx.x;
    if (e < E) {
        int r = ei[e];
        int c = ei[E + e];
        int pos = atomicAdd(&g_cur[c], 1);
        g_csrw[pos] = make_int2(r, __float_as_int(g_dinv[r]));
    }
}

// ---------------- fp16 HMMA GEMM: C[M,128] = A[M,128] @ W[128,128] ----------------
// smem: Wsu [128 n][69 uints]  (uint j of row n = {W[2j][n], W[2j+1][n]})
//       Asu [128 m][68 uints]  (uint j of row m = {A[m][2j], A[m][2j+1]})
#define WS_STRIDE 69
#define AS_STRIDE 68
#define GEMM_SMEM ((128 * WS_STRIDE + 128 * AS_STRIDE) * 4)

__device__ __forceinline__ void ldpack(const float* A, size_t off,
                                       unsigned& u0, unsigned& u1) {
    float4 v = *(const float4*)(A + off);
    __half2 h0 = __floats2half2_rn(v.x, v.y);
    __half2 h1 = __floats2half2_rn(v.z, v.w);
    u0 = *(unsigned*)&h0;
    u1 = *(unsigned*)&h1;
}
__device__ __forceinline__ void ldpack(const __half* A, size_t off,
                                       unsigned& u0, unsigned& u1) {
    uint2 r = *(const uint2*)(A + off);
    u0 = r.x;
    u1 = r.y;
}

template <typename T>
__global__ __launch_bounds__(256, 1) void k_gemm(const T* __restrict__ A,
                                                 const float* __restrict__ W,
                                                 __half* __restrict__ C, int M) {
    extern __shared__ unsigned smem[];
    unsigned* Wsu = smem;                     // [128][69]
    unsigned* Asu = smem + 128 * WS_STRIDE;   // [128][68]
    __half* Wsh = (__half*)Wsu;               // half view, row stride 138
    int tid = threadIdx.x;
    int m0 = blockIdx.x * 128;

    // load + transpose W: W[k][n] -> Wsh[n][k]
#pragma unroll
    for (int j = 0; j < 16; j++) {
        int idx = tid + j * 256;
        int k = idx >> 5;          // W row (k index)
        int c4 = idx & 31;         // n group of 4
        float4 v = *(const float4*)(W + k * 128 + c4 * 4);
        int n = c4 * 4;
        Wsh[(n + 0) * (2 * WS_STRIDE) + k] = __float2half_rn(v.x);
        Wsh[(n + 1) * (2 * WS_STRIDE) + k] = __float2half_rn(v.y);
        Wsh[(n + 2) * (2 * WS_STRIDE) + k] = __float2half_rn(v.z);
        Wsh[(n + 3) * (2 * WS_STRIDE) + k] = __float2half_rn(v.w);
    }
    // load A tile as half pairs
#pragma unroll
    for (int j = 0; j < 16; j++) {
        int idx = tid + j * 256;
        int row = idx >> 5;
        int c4 = idx & 31;
        int gr = m0 + row;
        unsigned u0 = 0, u1 = 0;
        if (gr < M) ldpack(A, (size_t)gr * 128 + c4 * 4, u0, u1);
        Asu[row * AS_STRIDE + c4 * 2] = u0;
        Asu[row * AS_STRIDE + c4 * 2 + 1] = u1;
    }
    __syncthreads();

    int lane = tid & 31;
    int wid = tid >> 5;
    int g = lane >> 2;
    int tg = lane & 3;
    int wr = wid * 16;

    float acc[64];
#pragma unroll
    for (int i = 0; i < 64; i++) acc[i] = 0.f;

#pragma unroll
    for (int s = 0; s < 8; s++) {
        int base = s * 8;
        unsigned a0 = Asu[(wr + g) * AS_STRIDE + base + tg];
        unsigned a1 = Asu[(wr + g + 8) * AS_STRIDE + base + tg];
        unsigned a2 = Asu[(wr + g) * AS_STRIDE + base + tg + 4];
        unsigned a3 = Asu[(wr + g + 8) * AS_STRIDE + base + tg + 4];
#pragma unroll
        for (int n0 = 0; n0 < 16; n0++) {
            unsigned b0 = Wsu[(n0 * 8 + g) * WS_STRIDE + base + tg];
            unsigned b1 = Wsu[(n0 * 8 + g) * WS_STRIDE + base + tg + 4];
            float* c = &acc[n0 * 4];
            asm volatile(
                "mma.sync.aligned.m16n8k16.row.col.f32.f16.f16.f32 "
                "{%0,%1,%2,%3}, {%4,%5,%6,%7}, {%8,%9}, {%0,%1,%2,%3};"
                : "+f"(c[0]), "+f"(c[1]), "+f"(c[2]), "+f"(c[3])
                : "r"(a0), "r"(a1), "r"(a2), "r"(a3), "r"(b0), "r"(b1));
        }
    }

    int r0 = m0 + wr + g;
    int r1 = r0 + 8;
#pragma unroll
    for (int n0 = 0; n0 < 16; n0++) {
        int col = n0 * 8 + 2 * tg;
        if (r0 < M)
            *(__half2*)(C + (size_t)r0 * 128 + col) =
                __floats2half2_rn(acc[n0 * 4 + 0], acc[n0 * 4 + 1]);
        if (r1 < M)
            *(__half2*)(C + (size_t)r1 * 128 + col) =
                __floats2half2_rn(acc[n0 * 4 + 2], acc[n0 * 4 + 3]);
    }
}

// ---------------- aggregation: warp per dst, 8 edges / warp-iteration ----------------
__device__ __forceinline__ void acc_row(float* acc, uint4 r, float w) {
    float2 f0 = __half22float2(*(__half2*)&r.x);
    float2 f1 = __half22float2(*(__half2*)&r.y);
    float2 f2 = __half22float2(*(__half2*)&r.z);
    float2 f3 = __half22float2(*(__half2*)&r.w);
    acc[0] += w * f0.x; acc[1] += w * f0.y;
    acc[2] += w * f1.x; acc[3] += w * f1.y;
    acc[4] += w * f2.x; acc[5] += w * f2.y;
    acc[6] += w * f3.x; acc[7] += w * f3.y;
}

__global__ void k_agg(const __half* __restrict__ hin, __half* __restrict__ hout,
                      const float* __restrict__ bias, int n) {
    int t = blockIdx.x * blockDim.x + threadIdx.x;
    int d = t >> 5;
    if (d >= n) return;
    int lane = t & 31;
    int hid = lane >> 4;
    int sub = lane & 15;

    const uint4* h4 = (const uint4*)hin;

    int4 nd = g_nd[d];
    int start = nd.x;
    int e = nd.y;
    float di = __int_as_float(nd.z);

    float acc[8];
#pragma unroll
    for (int k = 0; k < 8; k++) acc[k] = 0.f;

    if (hid == 0) {
        uint4 r = h4[(size_t)d * 16 + sub];
        acc_row(acc, r, di);
    }

    const int2* cp = g_csrw + start;

    int i0 = 0;
    for (; i0 + 8 <= e; i0 += 8) {
        int i = i0 + hid * 4;
        int2 ea = cp[i];
        int2 eb = cp[i + 1];
        int2 ec = cp[i + 2];
        int2 ed = cp[i + 3];
        uint4 ra = h4[(size_t)ea.x * 16 + sub];
        uint4 rb = h4[(size_t)eb.x * 16 + sub];
        uint4 rc = h4[(size_t)ec.x * 16 + sub];
        uint4 rd = h4[(size_t)ed.x * 16 + sub];
        acc_row(acc, ra, __int_as_float(ea.y));
        acc_row(acc, rb, __int_as_float(eb.y));
        acc_row(acc, rc, __int_as_float(ec.y));
        acc_row(acc, rd, __int_as_float(ed.y));
    }
    for (; i0 < e; i0 += 2) {
        int i = i0 + hid;
        if (i < e) {
            int2 ew = cp[i];
            uint4 r = h4[(size_t)ew.x * 16 + sub];
            acc_row(acc, r, __int_as_float(ew.y));
        }
    }

#pragma unroll
    for (int k = 0; k < 8; k++)
        acc[k] += __shfl_xor_sync(0xffffffffu, acc[k], 16);

    if (hid == 0) {
        float4 b0 = ((const float4*)bias)[sub * 2];
        float4 b1 = ((const float4*)bias)[sub * 2 + 1];
        acc[0] = fmaxf(di * acc[0] + b0.x, 0.f);
        acc[1] = fmaxf(di * acc[1] + b0.y, 0.f);
        acc[2] = fmaxf(di * acc[2] + b0.z, 0.f);
        acc[3] = fmaxf(di * acc[3] + b0.w, 0.f);
        acc[4] = fmaxf(di * acc[4] + b1.x, 0.f);
        acc[5] = fmaxf(di * acc[5] + b1.y, 0.f);
        acc[6] = fmaxf(di * acc[6] + b1.z, 0.f);
        acc[7] = fmaxf(di * acc[7] + b1.w, 0.f);
        __half2 o0 = __floats2half2_rn(acc[0], acc[1]);
        __half2 o1 = __floats2half2_rn(acc[2], acc[3]);
        __half2 o2 = __floats2half2_rn(acc[4], acc[5]);
        __half2 o3 = __floats2half2_rn(acc[6], acc[7]);
        uint4 o;
        o.x = *(unsigned*)&o0; o.y = *(unsigned*)&o1;
        o.z = *(unsigned*)&o2; o.w = *(unsigned*)&o3;
        ((uint4*)hout)[(size_t)d * 16 + sub] = o;
    }
}

// ---------------- mean pool + head MLP ----------------
__global__ void k_pool(const float* __restrict__ u,
                       const float* __restrict__ Wh1, const float* __restrict__ bh1,
                       const float* __restrict__ Wh2, const float* __restrict__ bh2,
                       float* __restrict__ out) {
    __shared__ float hcat[192];
    __shared__ float mid[128];
    int g = blockIdx.x;
    int t = threadIdx.x;   // 128

    int start = g_goff[g];
    int cnt = g_cnts[NMAX + g];
    float acc = 0.f;
    for (int i = 0; i < cnt; i++)
        acc += __half2float(g_Hh[(size_t)(start + i) * 128 + t]);
    hcat[t] = acc / fmaxf((float)cnt, 1.f);
    if (t < 64) hcat[128 + t] = u[g * 64 + t];
    __syncthreads();

    float m = bh1[t];
#pragma unroll 4
    for (int k = 0; k < 192; k++) m += hcat[k] * Wh1[k * 128 + t];
    mid[t] = fmaxf(m, 0.f);
    __syncthreads();

    if (t < 2) {
        float o = bh2[t];
        for (int k = 0; k < 128; k++) o += mid[k] * Wh2[k * 2 + t];
        out[g * 2 + t] = o;
    }
}

// ---------------- launch ----------------
extern "C" void kernel_launch(void* const* d_in, const int* in_sizes, int n_in,
                              void* d_out, int out_size) {
    const float* x     = (const float*)d_in[0];
    const int*   ei    = (const int*)d_in[1];
    const float* u     = (const float*)d_in[2];
    const int*   batch = (const int*)d_in[3];
    int wi = (n_in >= 13) ? 5 : 4;
    const float* W1  = (const float*)d_in[wi + 0];
    const float* b1  = (const float*)d_in[wi + 1];
    const float* W2  = (const float*)d_in[wi + 2];
    const float* b2  = (const float*)d_in[wi + 3];
    const float* Wh1 = (const float*)d_in[wi + 4];
    const float* bh1 = (const float*)d_in[wi + 5];
    const float* Wh2 = (const float*)d_in[wi + 6];
    const float* bh2 = (const float*)d_in[wi + 7];
    float* out = (float*)d_out;

    int N = in_sizes[0] / D;
    int E = in_sizes[1] / 2;
    int G = in_sizes[2] / 64;

    void *pP, *pH, *pCnts;
    cudaGetSymbolAddress(&pP, g_Ph);
    cudaGetSymbolAddress(&pH, g_Hh);
    cudaGetSymbolAddress(&pCnts, g_cnts);
    __half* P = (__half*)pP;
    __half* H = (__half*)pH;

    cudaFuncSetAttribute(k_gemm<float>,  cudaFuncAttributeMaxDynamicSharedMemorySize, GEMM_SMEM);
    cudaFuncSetAttribute(k_gemm<__half>, cudaFuncAttributeMaxDynamicSharedMemorySize, GEMM_SMEM);

    cudaMemsetAsync(pCnts, 0, (size_t)(NMAX + GMAX) * sizeof(int), 0);

    k_count<<<(E + 255) / 256, 256>>>(ei, E, batch, N);
    int nb = (N + 1023) / 1024;
    k_scanA<<<nb, 1024>>>(N);
    k_scanB<<<2, 1024>>>(nb, G);
    k_scanC<<<nb, 1024>>>(N);
    k_fill<<<(E + 255) / 256, 256>>>(ei, E);

    int mb = (N + 127) / 128;
    k_gemm<float><<<mb, 256, GEMM_SMEM>>>(x, W1, P, N);
    k_agg<<<(N * 32 + 255) / 256, 256>>>(P, H, b1, N);
    k_gemm<__half><<<mb, 256, GEMM_SMEM>>>(H, W2, P, N);
    k_agg<<<(N * 32 + 255) / 256, 256>>>(P, H, b2, N);

    k_pool<<<G, 128>>>(u, Wh1, bh1, Wh2, bh2, out);
}